// round 1
// baseline (speedup 1.0000x reference)
#include <cuda_runtime.h>
#include <cstdint>

#define NHEADS 16
#define DHEAD  64
#define NB     4
#define SEQ    2048
#define DMODEL 1024
#define NBH    (NB * NHEADS)   // 64
#define MTOK   (NB * SEQ)      // 8192

// ---- scratch (allocation-free contract: __device__ globals) ----
__device__ float g_q[(size_t)NBH * SEQ * DHEAD];    //  33.5 MB
__device__ float g_k[(size_t)NBH * SEQ * DHEAD];
__device__ float g_v[(size_t)NBH * SEQ * DHEAD];
__device__ float g_p[(size_t)NBH * SEQ * SEQ];      //   1 GiB scores/probs
__device__ float g_c[(size_t)MTOK * DMODEL];        //  33.5 MB ctx

// ---- tf32 helpers ----
__device__ __forceinline__ float tf32r(float x) {
    float r; asm("cvt.rna.tf32.f32 %0, %1;" : "=f"(r) : "f"(x)); return r;
}

__device__ __forceinline__ void mma8(float c[4], const uint32_t a[4], const uint32_t b[2]) {
    asm volatile(
        "mma.sync.aligned.m16n8k8.row.col.f32.tf32.tf32.f32 "
        "{%0,%1,%2,%3},{%4,%5,%6,%7},{%8,%9},{%0,%1,%2,%3};"
        : "+f"(c[0]), "+f"(c[1]), "+f"(c[2]), "+f"(c[3])
        : "r"(a[0]), "r"(a[1]), "r"(a[2]), "r"(a[3]), "r"(b[0]), "r"(b[1]));
}

// ============================================================================
// Kernel 1: QKV projection.  out_p[b][h][s][d] = (X @ W_p)[b*S+s][h*64+d]
// X: [8192 x 1024] rm, W: [1024 x 1024] rm. Tile 128x128x16, 256 thr, 8 warps.
// ============================================================================
__global__ void k_qkv(const float* __restrict__ X,
                      const float* __restrict__ Wq,
                      const float* __restrict__ Wk,
                      const float* __restrict__ Wv)
{
    const int p = blockIdx.z;
    const float* W = (p == 0) ? Wq : ((p == 1) ? Wk : Wv);
    float* out = (p == 0) ? g_q : ((p == 1) ? g_k : g_v);

    __shared__ float As[2][16][132];   // [k][m], padded
    __shared__ float Bs[2][16][132];   // [k][n], padded

    const int tid  = threadIdx.x;
    const int lane = tid & 31;
    const int warp = tid >> 5;
    const int wm = (warp & 3) * 32;
    const int wn = (warp >> 2) * 64;
    const int m0 = blockIdx.y * 128;
    const int n0 = blockIdx.x * 128;

    float acc[2][8][4];
    #pragma unroll
    for (int i = 0; i < 2; i++)
        #pragma unroll
        for (int j = 0; j < 8; j++)
            #pragma unroll
            for (int q = 0; q < 4; q++) acc[i][j][q] = 0.f;

    const int ar = tid >> 1;          // A row within tile (0..127)
    const int ak = (tid & 1) * 8;     // A k offset (0 or 8)
    const int bk = tid >> 4;          // B k row (0..15)
    const int bn = (tid & 15) * 8;    // B n offset

    const float* Aptr = X + (size_t)(m0 + ar) * DMODEL + ak;
    const float* Bptr = W + (size_t)bk * DMODEL + n0 + bn;

    float4 a0v, a1v, b0v, b1v;
    auto ldg = [&](int kt) {
        const float* ap = Aptr + kt * 16;
        a0v = *(const float4*)(ap);
        a1v = *(const float4*)(ap + 4);
        const float* bp = Bptr + (size_t)kt * 16 * DMODEL;
        b0v = *(const float4*)(bp);
        b1v = *(const float4*)(bp + 4);
    };
    auto sts = [&](int buf) {
        As[buf][ak + 0][ar] = tf32r(a0v.x);
        As[buf][ak + 1][ar] = tf32r(a0v.y);
        As[buf][ak + 2][ar] = tf32r(a0v.z);
        As[buf][ak + 3][ar] = tf32r(a0v.w);
        As[buf][ak + 4][ar] = tf32r(a1v.x);
        As[buf][ak + 5][ar] = tf32r(a1v.y);
        As[buf][ak + 6][ar] = tf32r(a1v.z);
        As[buf][ak + 7][ar] = tf32r(a1v.w);
        float4 c0 = make_float4(tf32r(b0v.x), tf32r(b0v.y), tf32r(b0v.z), tf32r(b0v.w));
        float4 c1 = make_float4(tf32r(b1v.x), tf32r(b1v.y), tf32r(b1v.z), tf32r(b1v.w));
        *(float4*)&Bs[buf][bk][bn]     = c0;
        *(float4*)&Bs[buf][bk][bn + 4] = c1;
    };

    ldg(0); sts(0); __syncthreads();

    for (int kt = 0; kt < DMODEL / 16; ++kt) {
        const int cur = kt & 1;
        if (kt < DMODEL / 16 - 1) ldg(kt + 1);
        #pragma unroll
        for (int ks = 0; ks < 16; ks += 8) {
            uint32_t a[2][4], b[8][2];
            #pragma unroll
            for (int i = 0; i < 2; i++) {
                const int r = wm + i * 16 + (lane >> 2);
                a[i][0] = __float_as_uint(As[cur][ks + (lane & 3)][r]);
                a[i][1] = __float_as_uint(As[cur][ks + (lane & 3)][r + 8]);
                a[i][2] = __float_as_uint(As[cur][ks + 4 + (lane & 3)][r]);
                a[i][3] = __float_as_uint(As[cur][ks + 4 + (lane & 3)][r + 8]);
            }
            #pragma unroll
            for (int j = 0; j < 8; j++) {
                const int c = wn + j * 8 + (lane >> 2);
                b[j][0] = __float_as_uint(Bs[cur][ks + (lane & 3)][c]);
                b[j][1] = __float_as_uint(Bs[cur][ks + 4 + (lane & 3)][c]);
            }
            #pragma unroll
            for (int i = 0; i < 2; i++)
                #pragma unroll
                for (int j = 0; j < 8; j++) mma8(acc[i][j], a[i], b[j]);
        }
        if (kt < DMODEL / 16 - 1) sts(cur ^ 1);
        __syncthreads();
    }

    // epilogue: write to [b][h][s][d]
    #pragma unroll
    for (int i = 0; i < 2; i++) {
        #pragma unroll
        for (int j = 0; j < 8; j++) {
            const int row = m0 + wm + i * 16 + (lane >> 2);
            const int col = n0 + wn + j * 8 + (lane & 3) * 2;
            #pragma unroll
            for (int q = 0; q < 4; q++) {
                const int m = row + (q >> 1) * 8;
                const int n = col + (q & 1);
                const int b_ = m >> 11, s = m & (SEQ - 1);
                const int h = n >> 6, d = n & (DHEAD - 1);
                out[((size_t)((b_ * NHEADS + h) * SEQ + s) << 6) + d] = acc[i][j][q];
            }
        }
    }
}

// ============================================================================
// Kernel 2: scores[bh][q][k] = scale * (Q @ K^T).  K-dim = 64 (4 tiles).
// ============================================================================
__global__ void k_scores()
{
    const int bh = blockIdx.z;
    const float* Q  = g_q + (size_t)bh * SEQ * DHEAD;
    const float* Km = g_k + (size_t)bh * SEQ * DHEAD;
    float* Sc = g_p + (size_t)bh * SEQ * SEQ;

    __shared__ float As[2][16][132];
    __shared__ float Bs[2][16][132];

    const int tid  = threadIdx.x;
    const int lane = tid & 31;
    const int warp = tid >> 5;
    const int wm = (warp & 3) * 32;
    const int wn = (warp >> 2) * 64;
    const int m0 = blockIdx.y * 128;
    const int n0 = blockIdx.x * 128;

    float acc[2][8][4];
    #pragma unroll
    for (int i = 0; i < 2; i++)
        #pragma unroll
        for (int j = 0; j < 8; j++)
            #pragma unroll
            for (int q = 0; q < 4; q++) acc[i][j][q] = 0.f;

    const int ar = tid >> 1;
    const int ak = (tid & 1) * 8;
    const float* Aptr = Q  + (size_t)(m0 + ar) * DHEAD + ak;
    const float* Bptr = Km + (size_t)(n0 + ar) * DHEAD + ak;

    float4 a0v, a1v, b0v, b1v;
    auto ldg = [&](int kt) {
        a0v = *(const float4*)(Aptr + kt * 16);
        a1v = *(const float4*)(Aptr + kt * 16 + 4);
        b0v = *(const float4*)(Bptr + kt * 16);
        b1v = *(const float4*)(Bptr + kt * 16 + 4);
    };
    auto sts = [&](int buf) {
        As[buf][ak + 0][ar] = tf32r(a0v.x);
        As[buf][ak + 1][ar] = tf32r(a0v.y);
        As[buf][ak + 2][ar] = tf32r(a0v.z);
        As[buf][ak + 3][ar] = tf32r(a0v.w);
        As[buf][ak + 4][ar] = tf32r(a1v.x);
        As[buf][ak + 5][ar] = tf32r(a1v.y);
        As[buf][ak + 6][ar] = tf32r(a1v.z);
        As[buf][ak + 7][ar] = tf32r(a1v.w);
        Bs[buf][ak + 0][ar] = tf32r(b0v.x);
        Bs[buf][ak + 1][ar] = tf32r(b0v.y);
        Bs[buf][ak + 2][ar] = tf32r(b0v.z);
        Bs[buf][ak + 3][ar] = tf32r(b0v.w);
        Bs[buf][ak + 4][ar] = tf32r(b1v.x);
        Bs[buf][ak + 5][ar] = tf32r(b1v.y);
        Bs[buf][ak + 6][ar] = tf32r(b1v.z);
        Bs[buf][ak + 7][ar] = tf32r(b1v.w);
    };

    ldg(0); sts(0); __syncthreads();

    for (int kt = 0; kt < DHEAD / 16; ++kt) {
        const int cur = kt & 1;
        if (kt < DHEAD / 16 - 1) ldg(kt + 1);
        #pragma unroll
        for (int ks = 0; ks < 16; ks += 8) {
            uint32_t a[2][4], b[8][2];
            #pragma unroll
            for (int i = 0; i < 2; i++) {
                const int r = wm + i * 16 + (lane >> 2);
                a[i][0] = __float_as_uint(As[cur][ks + (lane & 3)][r]);
                a[i][1] = __float_as_uint(As[cur][ks + (lane & 3)][r + 8]);
                a[i][2] = __float_as_uint(As[cur][ks + 4 + (lane & 3)][r]);
                a[i][3] = __float_as_uint(As[cur][ks + 4 + (lane & 3)][r + 8]);
            }
            #pragma unroll
            for (int j = 0; j < 8; j++) {
                const int c = wn + j * 8 + (lane >> 2);
                b[j][0] = __float_as_uint(Bs[cur][ks + (lane & 3)][c]);
                b[j][1] = __float_as_uint(Bs[cur][ks + 4 + (lane & 3)][c]);
            }
            #pragma unroll
            for (int i = 0; i < 2; i++)
                #pragma unroll
                for (int j = 0; j < 8; j++) mma8(acc[i][j], a[i], b[j]);
        }
        if (kt < DHEAD / 16 - 1) sts(cur ^ 1);
        __syncthreads();
    }

    const float scale = 0.125f;   // 64^-0.5
    #pragma unroll
    for (int i = 0; i < 2; i++) {
        #pragma unroll
        for (int j = 0; j < 8; j++) {
            const int row = m0 + wm + i * 16 + (lane >> 2);
            const int col = n0 + wn + j * 8 + (lane & 3) * 2;
            #pragma unroll
            for (int q = 0; q < 4; q++) {
                const int m = row + (q >> 1) * 8;
                const int n = col + (q & 1);
                Sc[(size_t)m * SEQ + n] = acc[i][j][q] * scale;
            }
        }
    }
}

// ============================================================================
// Kernel 3: row softmax over g_p (in place). 1 block / row, 256 thr.
// ============================================================================
__global__ void k_softmax()
{
    const size_t row = blockIdx.x;
    float4* p4 = (float4*)(g_p + row * SEQ);
    const int t = threadIdx.x;
    const int lane = t & 31, warp = t >> 5;
    __shared__ float sh[8];

    float4 v0 = p4[t];
    float4 v1 = p4[t + 256];

    float mx = fmaxf(fmaxf(fmaxf(v0.x, v0.y), fmaxf(v0.z, v0.w)),
                     fmaxf(fmaxf(v1.x, v1.y), fmaxf(v1.z, v1.w)));
    #pragma unroll
    for (int o = 16; o; o >>= 1) mx = fmaxf(mx, __shfl_xor_sync(0xffffffffu, mx, o));
    if (lane == 0) sh[warp] = mx;
    __syncthreads();
    mx = sh[0];
    #pragma unroll
    for (int i = 1; i < 8; i++) mx = fmaxf(mx, sh[i]);
    __syncthreads();

    v0.x = __expf(v0.x - mx); v0.y = __expf(v0.y - mx);
    v0.z = __expf(v0.z - mx); v0.w = __expf(v0.w - mx);
    v1.x = __expf(v1.x - mx); v1.y = __expf(v1.y - mx);
    v1.z = __expf(v1.z - mx); v1.w = __expf(v1.w - mx);

    float s = v0.x + v0.y + v0.z + v0.w + v1.x + v1.y + v1.z + v1.w;
    #pragma unroll
    for (int o = 16; o; o >>= 1) s += __shfl_xor_sync(0xffffffffu, s, o);
    if (lane == 0) sh[warp] = s;
    __syncthreads();
    s = sh[0];
    #pragma unroll
    for (int i = 1; i < 8; i++) s += sh[i];

    const float inv = 1.0f / s;
    v0.x *= inv; v0.y *= inv; v0.z *= inv; v0.w *= inv;
    v1.x *= inv; v1.y *= inv; v1.z *= inv; v1.w *= inv;
    p4[t] = v0;
    p4[t + 256] = v1;
}

// ============================================================================
// Kernel 4: ctx = P @ V, written as [b][s][h*64+d].  M=2048,N=64,K=2048 / bh.
// Tile 128x64x16. Warp tile 32x32 (2 m-frags, 4 n-frags).
// ============================================================================
__global__ void k_pv()
{
    const int bh = blockIdx.z;
    const int b_ = bh >> 4, h = bh & 15;
    const float* P = g_p + (size_t)bh * SEQ * SEQ;
    const float* V = g_v + (size_t)bh * SEQ * DHEAD;

    __shared__ float As[2][16][132];
    __shared__ float Bs[2][16][68];

    const int tid  = threadIdx.x;
    const int lane = tid & 31;
    const int warp = tid >> 5;
    const int wm = (warp & 3) * 32;
    const int wn = (warp >> 2) * 32;
    const int m0 = blockIdx.y * 128;

    float acc[2][4][4];
    #pragma unroll
    for (int i = 0; i < 2; i++)
        #pragma unroll
        for (int j = 0; j < 4; j++)
            #pragma unroll
            for (int q = 0; q < 4; q++) acc[i][j][q] = 0.f;

    const int ar = tid >> 1;
    const int ak = (tid & 1) * 8;
    const int bk = tid >> 4;          // 0..15
    const int bn = (tid & 15) * 4;    // 0..60

    const float* Aptr = P + (size_t)(m0 + ar) * SEQ + ak;
    const float* Bptr = V + (size_t)bk * DHEAD + bn;

    float4 a0v, a1v, b0v;
    auto ldg = [&](int kt) {
        a0v = *(const float4*)(Aptr + kt * 16);
        a1v = *(const float4*)(Aptr + kt * 16 + 4);
        b0v = *(const float4*)(Bptr + (size_t)kt * 16 * DHEAD);
    };
    auto sts = [&](int buf) {
        As[buf][ak + 0][ar] = tf32r(a0v.x);
        As[buf][ak + 1][ar] = tf32r(a0v.y);
        As[buf][ak + 2][ar] = tf32r(a0v.z);
        As[buf][ak + 3][ar] = tf32r(a0v.w);
        As[buf][ak + 4][ar] = tf32r(a1v.x);
        As[buf][ak + 5][ar] = tf32r(a1v.y);
        As[buf][ak + 6][ar] = tf32r(a1v.z);
        As[buf][ak + 7][ar] = tf32r(a1v.w);
        float4 c0 = make_float4(tf32r(b0v.x), tf32r(b0v.y), tf32r(b0v.z), tf32r(b0v.w));
        *(float4*)&Bs[buf][bk][bn] = c0;
    };

    ldg(0); sts(0); __syncthreads();

    for (int kt = 0; kt < SEQ / 16; ++kt) {
        const int cur = kt & 1;
        if (kt < SEQ / 16 - 1) ldg(kt + 1);
        #pragma unroll
        for (int ks = 0; ks < 16; ks += 8) {
            uint32_t a[2][4], b[4][2];
            #pragma unroll
            for (int i = 0; i < 2; i++) {
                const int r = wm + i * 16 + (lane >> 2);
                a[i][0] = __float_as_uint(As[cur][ks + (lane & 3)][r]);
                a[i][1] = __float_as_uint(As[cur][ks + (lane & 3)][r + 8]);
                a[i][2] = __float_as_uint(As[cur][ks + 4 + (lane & 3)][r]);
                a[i][3] = __float_as_uint(As[cur][ks + 4 + (lane & 3)][r + 8]);
            }
            #pragma unroll
            for (int j = 0; j < 4; j++) {
                const int c = wn + j * 8 + (lane >> 2);
                b[j][0] = __float_as_uint(Bs[cur][ks + (lane & 3)][c]);
                b[j][1] = __float_as_uint(Bs[cur][ks + 4 + (lane & 3)][c]);
            }
            #pragma unroll
            for (int i = 0; i < 2; i++)
                #pragma unroll
                for (int j = 0; j < 4; j++) mma8(acc[i][j], a[i], b[j]);
        }
        if (kt < SEQ / 16 - 1) sts(cur ^ 1);
        __syncthreads();
    }

    #pragma unroll
    for (int i = 0; i < 2; i++) {
        #pragma unroll
        for (int j = 0; j < 4; j++) {
            const int row = m0 + wm + i * 16 + (lane >> 2);
            const int col = wn + j * 8 + (lane & 3) * 2;
            #pragma unroll
            for (int q = 0; q < 4; q++) {
                const int m = row + (q >> 1) * 8;
                const int n = col + (q & 1);
                g_c[(size_t)(b_ * SEQ + m) * DMODEL + h * DHEAD + n] = acc[i][j][q];
            }
        }
    }
}

// ============================================================================
// Kernel 5: out = ctx @ Wo.  [8192x1024] @ [1024x1024], plain row-major out.
// ============================================================================
__global__ void k_oproj(const float* __restrict__ Wo, float* __restrict__ Out)
{
    __shared__ float As[2][16][132];
    __shared__ float Bs[2][16][132];

    const int tid  = threadIdx.x;
    const int lane = tid & 31;
    const int warp = tid >> 5;
    const int wm = (warp & 3) * 32;
    const int wn = (warp >> 2) * 64;
    const int m0 = blockIdx.y * 128;
    const int n0 = blockIdx.x * 128;

    float acc[2][8][4];
    #pragma unroll
    for (int i = 0; i < 2; i++)
        #pragma unroll
        for (int j = 0; j < 8; j++)
            #pragma unroll
            for (int q = 0; q < 4; q++) acc[i][j][q] = 0.f;

    const int ar = tid >> 1;
    const int ak = (tid & 1) * 8;
    const int bk = tid >> 4;
    const int bn = (tid & 15) * 8;

    const float* Aptr = g_c + (size_t)(m0 + ar) * DMODEL + ak;
    const float* Bptr = Wo + (size_t)bk * DMODEL + n0 + bn;

    float4 a0v, a1v, b0v, b1v;
    auto ldg = [&](int kt) {
        a0v = *(const float4*)(Aptr + kt * 16);
        a1v = *(const float4*)(Aptr + kt * 16 + 4);
        const float* bp = Bptr + (size_t)kt * 16 * DMODEL;
        b0v = *(const float4*)(bp);
        b1v = *(const float4*)(bp + 4);
    };
    auto sts = [&](int buf) {
        As[buf][ak + 0][ar] = tf32r(a0v.x);
        As[buf][ak + 1][ar] = tf32r(a0v.y);
        As[buf][ak + 2][ar] = tf32r(a0v.z);
        As[buf][ak + 3][ar] = tf32r(a0v.w);
        As[buf][ak + 4][ar] = tf32r(a1v.x);
        As[buf][ak + 5][ar] = tf32r(a1v.y);
        As[buf][ak + 6][ar] = tf32r(a1v.z);
        As[buf][ak + 7][ar] = tf32r(a1v.w);
        float4 c0 = make_float4(tf32r(b0v.x), tf32r(b0v.y), tf32r(b0v.z), tf32r(b0v.w));
        float4 c1 = make_float4(tf32r(b1v.x), tf32r(b1v.y), tf32r(b1v.z), tf32r(b1v.w));
        *(float4*)&Bs[buf][bk][bn]     = c0;
        *(float4*)&Bs[buf][bk][bn + 4] = c1;
    };

    ldg(0); sts(0); __syncthreads();

    for (int kt = 0; kt < DMODEL / 16; ++kt) {
        const int cur = kt & 1;
        if (kt < DMODEL / 16 - 1) ldg(kt + 1);
        #pragma unroll
        for (int ks = 0; ks < 16; ks += 8) {
            uint32_t a[2][4], b[8][2];
            #pragma unroll
            for (int i = 0; i < 2; i++) {
                const int r = wm + i * 16 + (lane >> 2);
                a[i][0] = __float_as_uint(As[cur][ks + (lane & 3)][r]);
                a[i][1] = __float_as_uint(As[cur][ks + (lane & 3)][r + 8]);
                a[i][2] = __float_as_uint(As[cur][ks + 4 + (lane & 3)][r]);
                a[i][3] = __float_as_uint(As[cur][ks + 4 + (lane & 3)][r + 8]);
            }
            #pragma unroll
            for (int j = 0; j < 8; j++) {
                const int c = wn + j * 8 + (lane >> 2);
                b[j][0] = __float_as_uint(Bs[cur][ks + (lane & 3)][c]);
                b[j][1] = __float_as_uint(Bs[cur][ks + 4 + (lane & 3)][c]);
            }
            #pragma unroll
            for (int i = 0; i < 2; i++)
                #pragma unroll
                for (int j = 0; j < 8; j++) mma8(acc[i][j], a[i], b[j]);
        }
        if (kt < DMODEL / 16 - 1) sts(cur ^ 1);
        __syncthreads();
    }

    #pragma unroll
    for (int i = 0; i < 2; i++) {
        #pragma unroll
        for (int j = 0; j < 8; j++) {
            const int row = m0 + wm + i * 16 + (lane >> 2);
            const int col = n0 + wn + j * 8 + (lane & 3) * 2;
            #pragma unroll
            for (int q = 0; q < 4; q++) {
                const int m = row + (q >> 1) * 8;
                const int n = col + (q & 1);
                Out[(size_t)m * DMODEL + n] = acc[i][j][q];
            }
        }
    }
}

// ============================================================================
extern "C" void kernel_launch(void* const* d_in, const int* in_sizes, int n_in,
                              void* d_out, int out_size)
{
    const float* x  = (const float*)d_in[0];
    const float* Wq = (const float*)d_in[1];
    const float* Wk = (const float*)d_in[2];
    const float* Wv = (const float*)d_in[3];
    const float* Wo = (const float*)d_in[4];
    float* out = (float*)d_out;

    k_qkv<<<dim3(8, 64, 3), 256>>>(x, Wq, Wk, Wv);
    k_scores<<<dim3(16, 16, 64), 256>>>();
    k_softmax<<<dim3(NBH * SEQ, 1, 1), 256>>>();
    k_pv<<<dim3(1, 16, 64), 256>>>();
    k_oproj<<<dim3(8, 64, 1), 256>>>(Wo, out);
}

// round 2
// speedup vs baseline: 1.6146x; 1.6146x over previous
#include <cuda_runtime.h>
#include <cstdint>

#define NHEADS 16
#define DHEAD  64
#define NB     4
#define SEQ    2048
#define DMODEL 1024
#define NBH    (NB * NHEADS)   // 64
#define MTOK   (NB * SEQ)      // 8192

// ---- scratch ----
__device__ float g_q[(size_t)NBH * SEQ * DHEAD];    // [bh][s][phi(d)], pre-scaled by 0.125*log2e, tf32
__device__ float g_k[(size_t)NBH * SEQ * DHEAD];    // [bh][s][phi(d)], tf32
__device__ float g_v[(size_t)NBH * DHEAD * SEQ];    // [bh][d][phi_s(s)], tf32  (transposed!)
__device__ float g_c[(size_t)MTOK * DMODEL];        // ctx [token][h*64+d]

#define QSCALE 0.18033688011112042f   /* 0.125 * log2(e) */

// within-8 interleave: logical k-positions {t, t+4} -> physical {2t, 2t+1}
__device__ __forceinline__ int phi8(int x) { return ((x & 3) << 1) | ((x >> 2) & 1); }
__device__ __forceinline__ int phid(int d) { return (d & ~7) | phi8(d & 7); }

__device__ __forceinline__ float tf32r(float x) {
    float r; asm("cvt.rna.tf32.f32 %0, %1;" : "=f"(r) : "f"(x)); return r;
}
__device__ __forceinline__ float ex2(float x) {
    float r; asm("ex2.approx.ftz.f32 %0, %1;" : "=f"(r) : "f"(x)); return r;
}

__device__ __forceinline__ void mma8(float c[4], const uint32_t a[4], const uint32_t b[2]) {
    asm volatile(
        "mma.sync.aligned.m16n8k8.row.col.f32.tf32.tf32.f32 "
        "{%0,%1,%2,%3},{%4,%5,%6,%7},{%8,%9},{%0,%1,%2,%3};"
        : "+f"(c[0]), "+f"(c[1]), "+f"(c[2]), "+f"(c[3])
        : "r"(a[0]), "r"(a[1]), "r"(a[2]), "r"(a[3]), "r"(b[0]), "r"(b[1]));
}
__device__ __forceinline__ void mma8f(float c[4], const float a[4], float b0, float b1) {
    uint32_t au[4] = {__float_as_uint(a[0]), __float_as_uint(a[1]),
                      __float_as_uint(a[2]), __float_as_uint(a[3])};
    uint32_t bu[2] = {__float_as_uint(b0), __float_as_uint(b1)};
    mma8(c, au, bu);
}

__device__ __forceinline__ void cpa16(uint32_t dst, const float* src) {
    asm volatile("cp.async.cg.shared.global [%0], [%1], 16;" :: "r"(dst), "l"(src));
}

// ============================================================================
// Kernel 1: QKV projection with flash-friendly epilogues.
// ============================================================================
__global__ void k_qkv(const float* __restrict__ X,
                      const float* __restrict__ Wq,
                      const float* __restrict__ Wk,
                      const float* __restrict__ Wv)
{
    const int p = blockIdx.z;
    const float* W = (p == 0) ? Wq : ((p == 1) ? Wk : Wv);

    __shared__ float As[2][16][132];
    __shared__ float Bs[2][16][132];

    const int tid  = threadIdx.x;
    const int lane = tid & 31;
    const int warp = tid >> 5;
    const int wm = (warp & 3) * 32;
    const int wn = (warp >> 2) * 64;
    const int m0 = blockIdx.y * 128;
    const int n0 = blockIdx.x * 128;

    float acc[2][8][4];
    #pragma unroll
    for (int i = 0; i < 2; i++)
        #pragma unroll
        for (int j = 0; j < 8; j++)
            #pragma unroll
            for (int q = 0; q < 4; q++) acc[i][j][q] = 0.f;

    const int ar = tid >> 1;
    const int ak = (tid & 1) * 8;
    const int bk = tid >> 4;
    const int bn = (tid & 15) * 8;

    const float* Aptr = X + (size_t)(m0 + ar) * DMODEL + ak;
    const float* Bptr = W + (size_t)bk * DMODEL + n0 + bn;

    float4 a0v, a1v, b0v, b1v;
    auto ldg = [&](int kt) {
        const float* ap = Aptr + kt * 16;
        a0v = *(const float4*)(ap);
        a1v = *(const float4*)(ap + 4);
        const float* bp = Bptr + (size_t)kt * 16 * DMODEL;
        b0v = *(const float4*)(bp);
        b1v = *(const float4*)(bp + 4);
    };
    auto sts = [&](int buf) {
        As[buf][ak + 0][ar] = tf32r(a0v.x);
        As[buf][ak + 1][ar] = tf32r(a0v.y);
        As[buf][ak + 2][ar] = tf32r(a0v.z);
        As[buf][ak + 3][ar] = tf32r(a0v.w);
        As[buf][ak + 4][ar] = tf32r(a1v.x);
        As[buf][ak + 5][ar] = tf32r(a1v.y);
        As[buf][ak + 6][ar] = tf32r(a1v.z);
        As[buf][ak + 7][ar] = tf32r(a1v.w);
        float4 c0 = make_float4(tf32r(b0v.x), tf32r(b0v.y), tf32r(b0v.z), tf32r(b0v.w));
        float4 c1 = make_float4(tf32r(b1v.x), tf32r(b1v.y), tf32r(b1v.z), tf32r(b1v.w));
        *(float4*)&Bs[buf][bk][bn]     = c0;
        *(float4*)&Bs[buf][bk][bn + 4] = c1;
    };

    ldg(0); sts(0); __syncthreads();

    for (int kt = 0; kt < DMODEL / 16; ++kt) {
        const int cur = kt & 1;
        if (kt < DMODEL / 16 - 1) ldg(kt + 1);
        #pragma unroll
        for (int ks = 0; ks < 16; ks += 8) {
            uint32_t a[2][4], b[8][2];
            #pragma unroll
            for (int i = 0; i < 2; i++) {
                const int r = wm + i * 16 + (lane >> 2);
                a[i][0] = __float_as_uint(As[cur][ks + (lane & 3)][r]);
                a[i][1] = __float_as_uint(As[cur][ks + (lane & 3)][r + 8]);
                a[i][2] = __float_as_uint(As[cur][ks + 4 + (lane & 3)][r]);
                a[i][3] = __float_as_uint(As[cur][ks + 4 + (lane & 3)][r + 8]);
            }
            #pragma unroll
            for (int j = 0; j < 8; j++) {
                const int c = wn + j * 8 + (lane >> 2);
                b[j][0] = __float_as_uint(Bs[cur][ks + (lane & 3)][c]);
                b[j][1] = __float_as_uint(Bs[cur][ks + 4 + (lane & 3)][c]);
            }
            #pragma unroll
            for (int i = 0; i < 2; i++)
                #pragma unroll
                for (int j = 0; j < 8; j++) mma8(acc[i][j], a[i], b[j]);
        }
        if (kt < DMODEL / 16 - 1) sts(cur ^ 1);
        __syncthreads();
    }

    #pragma unroll
    for (int i = 0; i < 2; i++) {
        #pragma unroll
        for (int j = 0; j < 8; j++) {
            const int row = m0 + wm + i * 16 + (lane >> 2);
            const int col = n0 + wn + j * 8 + (lane & 3) * 2;
            #pragma unroll
            for (int q = 0; q < 4; q++) {
                const int m = row + (q >> 1) * 8;
                const int n = col + (q & 1);
                const int b_ = m >> 11, s = m & (SEQ - 1);
                const int h = n >> 6, d = n & (DHEAD - 1);
                const int bh = b_ * NHEADS + h;
                float v = acc[i][j][q];
                if (p == 0) {
                    g_q[((size_t)bh * SEQ + s) * DHEAD + phid(d)] = tf32r(v * QSCALE);
                } else if (p == 1) {
                    g_k[((size_t)bh * SEQ + s) * DHEAD + phid(d)] = tf32r(v);
                } else {
                    g_v[((size_t)bh * DHEAD + d) * SEQ + (s & ~7) + phi8(s & 7)] = tf32r(v);
                }
            }
        }
    }
}

// ============================================================================
// Kernel 2: flash attention.  CTA = (q-tile 128, bh). 256 thr, 8 warps x 16 rows.
// K tile: Ks[2][128][72] row=key, col=phi(d). V tile: Vs[2][64][136] row=d, col=phi(key).
// ============================================================================
#define KPAD 72
#define VPAD 136
#define SMEM_FLASH ((2*128*KPAD + 2*64*VPAD) * 4)

__global__ void __launch_bounds__(256, 1) k_flash()
{
    extern __shared__ float sm[];
    float* Ks = sm;                      // [2][128][KPAD]
    float* Vs = sm + 2 * 128 * KPAD;     // [2][64][VPAD]

    const int bh = blockIdx.y;
    const int q0 = blockIdx.x * 128;
    const int tid = threadIdx.x, lane = tid & 31, warp = tid >> 5;
    const int u = lane >> 2, t = lane & 3;

    const float* gK = g_k + (size_t)bh * SEQ * DHEAD;
    const float* gV = g_v + (size_t)bh * DHEAD * SEQ;
    const float* gQ = g_q + (size_t)bh * SEQ * DHEAD;

    // Q fragments in registers for the whole kernel (pre-scaled, tf32, phi-layout)
    const int r = warp * 16 + u;
    float qa[8][4];
    {
        const float* qlo = gQ + (size_t)(q0 + r) * DHEAD;
        const float* qhi = qlo + 8 * DHEAD;
        #pragma unroll
        for (int kk = 0; kk < 8; kk++) {
            float2 lo = *(const float2*)(qlo + 8 * kk + 2 * t);
            float2 hi = *(const float2*)(qhi + 8 * kk + 2 * t);
            qa[kk][0] = lo.x; qa[kk][2] = lo.y;
            qa[kk][1] = hi.x; qa[kk][3] = hi.y;
        }
    }

    float o[8][4];
    #pragma unroll
    for (int j = 0; j < 8; j++)
        #pragma unroll
        for (int q = 0; q < 4; q++) o[j][q] = 0.f;
    float m0 = -1e30f, m1 = -1e30f, l0 = 0.f, l1 = 0.f;

    // async tile loader
    const int kRow = tid >> 1, kCol = (tid & 1) * 32;
    const int vRow = tid >> 2, vCol = (tid & 3) * 32;
    uint32_t ksBase = (uint32_t)__cvta_generic_to_shared(Ks);
    uint32_t vsBase = (uint32_t)__cvta_generic_to_shared(Vs);

    auto loadKV = [&](int kt, int bf) {
        const float* sK = gK + ((size_t)kt * 128 + kRow) * DHEAD + kCol;
        uint32_t dK = ksBase + (bf * 128 * KPAD + kRow * KPAD + kCol) * 4;
        #pragma unroll
        for (int i = 0; i < 8; i++) cpa16(dK + 16 * i, sK + 4 * i);
        const float* sV = gV + (size_t)vRow * SEQ + kt * 128 + vCol;
        uint32_t dV = vsBase + (bf * 64 * VPAD + vRow * VPAD + vCol) * 4;
        #pragma unroll
        for (int i = 0; i < 8; i++) cpa16(dV + 16 * i, sV + 4 * i);
        asm volatile("cp.async.commit_group;");
    };

    loadKV(0, 0);

    const int s0 = (lane & ~3) | (t >> 1);
    const int s1 = s0 + 2;
    const bool sel = (t & 1) != 0;

    for (int kt = 0; kt < SEQ / 128; ++kt) {
        const int cur = kt & 1;
        if (kt < SEQ / 128 - 1) loadKV(kt + 1, cur ^ 1);
        if (kt < SEQ / 128 - 1) asm volatile("cp.async.wait_group 1;");
        else                    asm volatile("cp.async.wait_group 0;");
        __syncthreads();

        // ---- S = Q K^T (pre-scaled into Q) ----
        float sc[16][4];
        #pragma unroll
        for (int j = 0; j < 16; j++)
            #pragma unroll
            for (int q = 0; q < 4; q++) sc[j][q] = 0.f;

        const float* pK = Ks + cur * 128 * KPAD + u * KPAD + 2 * t;
        #pragma unroll
        for (int kk = 0; kk < 8; kk++) {
            #pragma unroll
            for (int j = 0; j < 16; j++) {
                float2 b = *(const float2*)(pK + j * 8 * KPAD + kk * 8);
                mma8f(sc[j], qa[kk], b.x, b.y);
            }
        }

        // ---- online softmax (base-2) ----
        float tm0 = -1e30f, tm1 = -1e30f;
        #pragma unroll
        for (int j = 0; j < 16; j++) {
            tm0 = fmaxf(tm0, fmaxf(sc[j][0], sc[j][1]));
            tm1 = fmaxf(tm1, fmaxf(sc[j][2], sc[j][3]));
        }
        tm0 = fmaxf(tm0, __shfl_xor_sync(0xffffffffu, tm0, 1));
        tm0 = fmaxf(tm0, __shfl_xor_sync(0xffffffffu, tm0, 2));
        tm1 = fmaxf(tm1, __shfl_xor_sync(0xffffffffu, tm1, 1));
        tm1 = fmaxf(tm1, __shfl_xor_sync(0xffffffffu, tm1, 2));

        const float nm0 = fmaxf(m0, tm0), nm1 = fmaxf(m1, tm1);
        const float al0 = ex2(m0 - nm0), al1 = ex2(m1 - nm1);
        m0 = nm0; m1 = nm1;

        float rs0 = 0.f, rs1 = 0.f;
        #pragma unroll
        for (int j = 0; j < 16; j++) {
            float p0 = tf32r(ex2(sc[j][0] - nm0));
            float p1 = tf32r(ex2(sc[j][1] - nm0));
            float p2 = tf32r(ex2(sc[j][2] - nm1));
            float p3 = tf32r(ex2(sc[j][3] - nm1));
            sc[j][0] = p0; sc[j][1] = p1; sc[j][2] = p2; sc[j][3] = p3;
            rs0 += p0 + p1; rs1 += p2 + p3;
        }
        rs0 += __shfl_xor_sync(0xffffffffu, rs0, 1);
        rs0 += __shfl_xor_sync(0xffffffffu, rs0, 2);
        rs1 += __shfl_xor_sync(0xffffffffu, rs1, 1);
        rs1 += __shfl_xor_sync(0xffffffffu, rs1, 2);
        l0 = l0 * al0 + rs0;
        l1 = l1 * al1 + rs1;

        #pragma unroll
        for (int j = 0; j < 8; j++) {
            o[j][0] *= al0; o[j][1] *= al0;
            o[j][2] *= al1; o[j][3] *= al1;
        }

        // ---- O += P V ----
        const float* pV = Vs + cur * 64 * VPAD + u * VPAD + 2 * t;
        #pragma unroll
        for (int kk = 0; kk < 16; kk++) {
            float av[4];
            {
                float x0 = __shfl_sync(0xffffffffu, sc[kk][0], s0);
                float x1 = __shfl_sync(0xffffffffu, sc[kk][1], s0);
                av[0] = sel ? x1 : x0;
                x0 = __shfl_sync(0xffffffffu, sc[kk][2], s0);
                x1 = __shfl_sync(0xffffffffu, sc[kk][3], s0);
                av[1] = sel ? x1 : x0;
                x0 = __shfl_sync(0xffffffffu, sc[kk][0], s1);
                x1 = __shfl_sync(0xffffffffu, sc[kk][1], s1);
                av[2] = sel ? x1 : x0;
                x0 = __shfl_sync(0xffffffffu, sc[kk][2], s1);
                x1 = __shfl_sync(0xffffffffu, sc[kk][3], s1);
                av[3] = sel ? x1 : x0;
            }
            #pragma unroll
            for (int j = 0; j < 8; j++) {
                float2 b = *(const float2*)(pV + j * 8 * VPAD + kk * 8);
                mma8f(o[j], av, b.x, b.y);
            }
        }
        __syncthreads();
    }

    // ---- normalize and write ctx [token][h*64+d] ----
    const float i0 = 1.0f / l0, i1 = 1.0f / l1;
    const int b_ = bh >> 4, h = bh & 15;
    const int row0 = q0 + r;
    #pragma unroll
    for (int j = 0; j < 8; j++) {
        const int d0 = 8 * j + 2 * t;
        float2 lo = make_float2(o[j][0] * i0, o[j][1] * i0);
        float2 hi = make_float2(o[j][2] * i1, o[j][3] * i1);
        *(float2*)&g_c[(size_t)(b_ * SEQ + row0) * DMODEL + h * DHEAD + d0] = lo;
        *(float2*)&g_c[(size_t)(b_ * SEQ + row0 + 8) * DMODEL + h * DHEAD + d0] = hi;
    }
}

// ============================================================================
// Kernel 3: out = ctx @ Wo.
// ============================================================================
__global__ void k_oproj(const float* __restrict__ Wo, float* __restrict__ Out)
{
    __shared__ float As[2][16][132];
    __shared__ float Bs[2][16][132];

    const int tid  = threadIdx.x;
    const int lane = tid & 31;
    const int warp = tid >> 5;
    const int wm = (warp & 3) * 32;
    const int wn = (warp >> 2) * 64;
    const int m0 = blockIdx.y * 128;
    const int n0 = blockIdx.x * 128;

    float acc[2][8][4];
    #pragma unroll
    for (int i = 0; i < 2; i++)
        #pragma unroll
        for (int j = 0; j < 8; j++)
            #pragma unroll
            for (int q = 0; q < 4; q++) acc[i][j][q] = 0.f;

    const int ar = tid >> 1;
    const int ak = (tid & 1) * 8;
    const int bk = tid >> 4;
    const int bn = (tid & 15) * 8;

    const float* Aptr = g_c + (size_t)(m0 + ar) * DMODEL + ak;
    const float* Bptr = Wo + (size_t)bk * DMODEL + n0 + bn;

    float4 a0v, a1v, b0v, b1v;
    auto ldg = [&](int kt) {
        a0v = *(const float4*)(Aptr + kt * 16);
        a1v = *(const float4*)(Aptr + kt * 16 + 4);
        const float* bp = Bptr + (size_t)kt * 16 * DMODEL;
        b0v = *(const float4*)(bp);
        b1v = *(const float4*)(bp + 4);
    };
    auto sts = [&](int buf) {
        As[buf][ak + 0][ar] = tf32r(a0v.x);
        As[buf][ak + 1][ar] = tf32r(a0v.y);
        As[buf][ak + 2][ar] = tf32r(a0v.z);
        As[buf][ak + 3][ar] = tf32r(a0v.w);
        As[buf][ak + 4][ar] = tf32r(a1v.x);
        As[buf][ak + 5][ar] = tf32r(a1v.y);
        As[buf][ak + 6][ar] = tf32r(a1v.z);
        As[buf][ak + 7][ar] = tf32r(a1v.w);
        float4 c0 = make_float4(tf32r(b0v.x), tf32r(b0v.y), tf32r(b0v.z), tf32r(b0v.w));
        float4 c1 = make_float4(tf32r(b1v.x), tf32r(b1v.y), tf32r(b1v.z), tf32r(b1v.w));
        *(float4*)&Bs[buf][bk][bn]     = c0;
        *(float4*)&Bs[buf][bk][bn + 4] = c1;
    };

    ldg(0); sts(0); __syncthreads();

    for (int kt = 0; kt < DMODEL / 16; ++kt) {
        const int cur = kt & 1;
        if (kt < DMODEL / 16 - 1) ldg(kt + 1);
        #pragma unroll
        for (int ks = 0; ks < 16; ks += 8) {
            uint32_t a[2][4], b[8][2];
            #pragma unroll
            for (int i = 0; i < 2; i++) {
                const int r = wm + i * 16 + (lane >> 2);
                a[i][0] = __float_as_uint(As[cur][ks + (lane & 3)][r]);
                a[i][1] = __float_as_uint(As[cur][ks + (lane & 3)][r + 8]);
                a[i][2] = __float_as_uint(As[cur][ks + 4 + (lane & 3)][r]);
                a[i][3] = __float_as_uint(As[cur][ks + 4 + (lane & 3)][r + 8]);
            }
            #pragma unroll
            for (int j = 0; j < 8; j++) {
                const int c = wn + j * 8 + (lane >> 2);
                b[j][0] = __float_as_uint(Bs[cur][ks + (lane & 3)][c]);
                b[j][1] = __float_as_uint(Bs[cur][ks + 4 + (lane & 3)][c]);
            }
            #pragma unroll
            for (int i = 0; i < 2; i++)
                #pragma unroll
                for (int j = 0; j < 8; j++) mma8(acc[i][j], a[i], b[j]);
        }
        if (kt < DMODEL / 16 - 1) sts(cur ^ 1);
        __syncthreads();
    }

    #pragma unroll
    for (int i = 0; i < 2; i++) {
        #pragma unroll
        for (int j = 0; j < 8; j++) {
            const int row = m0 + wm + i * 16 + (lane >> 2);
            const int col = n0 + wn + j * 8 + (lane & 3) * 2;
            #pragma unroll
            for (int q = 0; q < 4; q++) {
                const int m = row + (q >> 1) * 8;
                const int n = col + (q & 1);
                Out[(size_t)m * DMODEL + n] = acc[i][j][q];
            }
        }
    }
}

// ============================================================================
extern "C" void kernel_launch(void* const* d_in, const int* in_sizes, int n_in,
                              void* d_out, int out_size)
{
    const float* x  = (const float*)d_in[0];
    const float* Wq = (const float*)d_in[1];
    const float* Wk = (const float*)d_in[2];
    const float* Wv = (const float*)d_in[3];
    const float* Wo = (const float*)d_in[4];
    float* out = (float*)d_out;

    static int smem_set = 0;
    if (!smem_set) {
        cudaFuncSetAttribute(k_flash, cudaFuncAttributeMaxDynamicSharedMemorySize, SMEM_FLASH);
        smem_set = 1;
    }

    k_qkv<<<dim3(8, 64, 3), 256>>>(x, Wq, Wk, Wv);
    k_flash<<<dim3(16, 64), 256, SMEM_FLASH>>>();
    k_oproj<<<dim3(8, 64, 1), 256>>>(Wo, out);
}

// round 4
// speedup vs baseline: 1.8207x; 1.1276x over previous
#include <cuda_runtime.h>
#include <cstdint>

#define NHEADS 16
#define DHEAD  64
#define NB     4
#define SEQ    2048
#define DMODEL 1024
#define NBH    (NB * NHEADS)   // 64
#define MTOK   (NB * SEQ)      // 8192

#define QSCALE 0.18033688011112042f   /* 0.125 * log2(e) */

// ---- scratch ----
__device__ float g_xr[(size_t)MTOK * DMODEL];        // x, tf32-rounded
__device__ float g_wt[4][(size_t)DMODEL * DMODEL];   // W^T [n][k], tf32 (q,k,v,o)
__device__ float g_q[(size_t)NBH * SEQ * DHEAD];     // [bh][s][phi(d)], *QSCALE, tf32
__device__ float g_k[(size_t)NBH * SEQ * DHEAD];     // [bh][s][d], tf32
__device__ float g_v[(size_t)NBH * DHEAD * SEQ];     // [bh][d][s], tf32
__device__ float g_c[(size_t)MTOK * DMODEL];         // ctx, tf32-rounded

// within-8 interleave for Q only: logical {t, t+4} -> physical {2t, 2t+1}
__device__ __forceinline__ int phi8(int x) { return ((x & 3) << 1) | ((x >> 2) & 1); }
__device__ __forceinline__ int phid(int d) { return (d & ~7) | phi8(d & 7); }

__device__ __forceinline__ float tf32r(float x) {
    float r; asm("cvt.rna.tf32.f32 %0, %1;" : "=f"(r) : "f"(x)); return r;
}
__device__ __forceinline__ float ex2(float x) {
    float r; asm("ex2.approx.ftz.f32 %0, %1;" : "=f"(r) : "f"(x)); return r;
}
__device__ __forceinline__ void mma8(float c[4], const uint32_t a[4], const uint32_t b[2]) {
    asm volatile(
        "mma.sync.aligned.m16n8k8.row.col.f32.tf32.tf32.f32 "
        "{%0,%1,%2,%3},{%4,%5,%6,%7},{%8,%9},{%0,%1,%2,%3};"
        : "+f"(c[0]), "+f"(c[1]), "+f"(c[2]), "+f"(c[3])
        : "r"(a[0]), "r"(a[1]), "r"(a[2]), "r"(a[3]), "r"(b[0]), "r"(b[1]));
}
__device__ __forceinline__ void mma8f(float c[4], const float a[4], uint32_t b0, uint32_t b1) {
    uint32_t au[4] = {__float_as_uint(a[0]), __float_as_uint(a[1]),
                      __float_as_uint(a[2]), __float_as_uint(a[3])};
    uint32_t bu[2] = {b0, b1};
    mma8(c, au, bu);
}
__device__ __forceinline__ void ldsm4(uint32_t& r0, uint32_t& r1, uint32_t& r2, uint32_t& r3,
                                      uint32_t addr) {
    asm volatile("ldmatrix.sync.aligned.m8n8.x4.shared.b16 {%0,%1,%2,%3}, [%4];"
                 : "=r"(r0), "=r"(r1), "=r"(r2), "=r"(r3) : "r"(addr));
}
__device__ __forceinline__ void cpa16(uint32_t dst, const float* src) {
    asm volatile("cp.async.cg.shared.global [%0], [%1], 16;" :: "r"(dst), "l"(src));
}

// ============================================================================
// Pre-pass 1: round x -> tf32
// ============================================================================
__global__ void k_roundx(const float4* __restrict__ X)
{
    const size_t i = (size_t)blockIdx.x * blockDim.x + threadIdx.x;
    float4 v = X[i];
    ((float4*)g_xr)[i] = make_float4(tf32r(v.x), tf32r(v.y), tf32r(v.z), tf32r(v.w));
}

// ============================================================================
// Pre-pass 2: transpose+round weights:  g_wt[p][n][k] = tf32(W_p[k][n])
// ============================================================================
__global__ void k_trw(const float* __restrict__ Wq, const float* __restrict__ Wk,
                      const float* __restrict__ Wv, const float* __restrict__ Wo)
{
    const int p = blockIdx.z;
    const float* W = (p == 0) ? Wq : (p == 1) ? Wk : (p == 2) ? Wv : Wo;
    __shared__ float t[32][33];
    const int n0 = blockIdx.x * 32, k0 = blockIdx.y * 32;
    const int tx = threadIdx.x, ty = threadIdx.y;
    #pragma unroll
    for (int i = 0; i < 4; i++)
        t[ty + 8 * i][tx] = W[(size_t)(k0 + ty + 8 * i) * DMODEL + n0 + tx];
    __syncthreads();
    float* out = g_wt[p];
    #pragma unroll
    for (int i = 0; i < 4; i++)
        out[(size_t)(n0 + ty + 8 * i) * DMODEL + k0 + tx] = tf32r(t[tx][ty + 8 * i]);
}

// ============================================================================
// Projection GEMM: 128x128 tile, k-tile 32, cp.async + ldmatrix.
// mode 0/1/2 = Q/K/V proj (A=g_xr), mode 3 = output proj (A=g_c, writes Out).
// Smem: A[2][128][32] + B[2][128][32] floats, XOR-swizzled 16B chunks. 64KB.
// ============================================================================
__global__ void __launch_bounds__(256, 2) k_proj(int mode_base, float* __restrict__ Out)
{
    extern __shared__ char sm[];
    const uint32_t sb = (uint32_t)__cvta_generic_to_shared(sm);
    const uint32_t AsB = sb, BsB = sb + 32768;

    const int mode = mode_base + blockIdx.z;
    const float* A = (mode < 3) ? g_xr : g_c;
    const float* Bt = g_wt[mode];

    const int tid = threadIdx.x, lane = tid & 31, warp = tid >> 5;
    const int wm = (warp & 3) * 32, wn = (warp >> 2) * 64;
    const int m0 = blockIdx.y * 128, n0 = blockIdx.x * 128;

    float acc[2][8][4];
    #pragma unroll
    for (int i = 0; i < 2; i++)
        #pragma unroll
        for (int j = 0; j < 8; j++)
            #pragma unroll
            for (int q = 0; q < 4; q++) acc[i][j][q] = 0.f;

    // loader: row = tid>>1 (0..127), half = tid&1 -> chunks 4h..4h+3
    const int lr = tid >> 1, lh = tid & 1;
    const float* Ap = A  + (size_t)(m0 + lr) * DMODEL + lh * 16;
    const float* Bp = Bt + (size_t)(n0 + lr) * DMODEL + lh * 16;
    uint32_t offs[4];
    #pragma unroll
    for (int i = 0; i < 4; i++) {
        const int c = 4 * lh + i;
        offs[i] = lr * 128 + ((c ^ (lr & 7)) << 4);
    }
    auto load = [&](int kt, int buf) {
        const float* a = Ap + kt * 32;
        const float* b = Bp + kt * 32;
        #pragma unroll
        for (int i = 0; i < 4; i++) cpa16(AsB + buf * 16384 + offs[i], a + 4 * i);
        #pragma unroll
        for (int i = 0; i < 4; i++) cpa16(BsB + buf * 16384 + offs[i], b + 4 * i);
        asm volatile("cp.async.commit_group;");
    };

    const int lrow = ((lane >> 3) & 1) * 8 + (lane & 7);
    const int lch  = lane >> 4;

    load(0, 0);

    for (int kt = 0; kt < DMODEL / 32; ++kt) {
        const int cur = kt & 1;
        if (kt < DMODEL / 32 - 1) load(kt + 1, cur ^ 1);
        if (kt < DMODEL / 32 - 1) asm volatile("cp.async.wait_group 1;");
        else                      asm volatile("cp.async.wait_group 0;");
        __syncthreads();

        const uint32_t Ab = AsB + cur * 16384, Bb = BsB + cur * 16384;
        #pragma unroll
        for (int s = 0; s < 4; s++) {
            uint32_t a[2][4], b[8][2];
            #pragma unroll
            for (int i = 0; i < 2; i++) {
                const int r = wm + i * 16 + lrow;
                const int c = 2 * s + lch;
                ldsm4(a[i][0], a[i][1], a[i][2], a[i][3],
                      Ab + r * 128 + ((c ^ (r & 7)) << 4));
            }
            #pragma unroll
            for (int jp = 0; jp < 4; jp++) {
                const int r = wn + jp * 16 + lrow;
                const int c = 2 * s + lch;
                ldsm4(b[2 * jp][0], b[2 * jp + 1][0], b[2 * jp][1], b[2 * jp + 1][1],
                      Bb + r * 128 + ((c ^ (r & 7)) << 4));
            }
            #pragma unroll
            for (int i = 0; i < 2; i++)
                #pragma unroll
                for (int j = 0; j < 8; j++) mma8(acc[i][j], a[i], b[j]);
        }
        __syncthreads();
    }

    // epilogue
    #pragma unroll
    for (int i = 0; i < 2; i++) {
        #pragma unroll
        for (int j = 0; j < 8; j++) {
            const int row = m0 + wm + i * 16 + (lane >> 2);
            const int col = n0 + wn + j * 8 + (lane & 3) * 2;
            #pragma unroll
            for (int q = 0; q < 4; q++) {
                const int m = row + (q >> 1) * 8;
                const int n = col + (q & 1);
                const float v = acc[i][j][q];
                if (mode == 3) {
                    Out[(size_t)m * DMODEL + n] = v;
                } else {
                    const int b_ = m >> 11, s = m & (SEQ - 1);
                    const int h = n >> 6, d = n & (DHEAD - 1);
                    const int bh = b_ * NHEADS + h;
                    if (mode == 0)
                        g_q[((size_t)bh * SEQ + s) * DHEAD + phid(d)] = tf32r(v * QSCALE);
                    else if (mode == 1)
                        g_k[((size_t)bh * SEQ + s) * DHEAD + d] = tf32r(v);
                    else
                        g_v[((size_t)bh * DHEAD + d) * SEQ + s] = tf32r(v);
                }
            }
        }
    }
}

// ============================================================================
// Flash attention. CTA = (q-tile 128, bh). 256 thr, 8 warps x 16 q-rows.
// Ks[2][128][64] (row=key), Vs[2][64][128] (row=d), Ps[8][16][128] (P staging),
// all XOR-swizzled 16B chunks. 192KB dynamic smem.
// ============================================================================
#define SMEM_FLASH 196608

__global__ void __launch_bounds__(256, 1) k_flash()
{
    extern __shared__ char sm[];
    const uint32_t sb  = (uint32_t)__cvta_generic_to_shared(sm);
    const uint32_t KsB = sb, VsB = sb + 65536, PsB = sb + 131072;

    const int bh = blockIdx.y;
    const int q0 = blockIdx.x * 128;
    const int tid = threadIdx.x, lane = tid & 31, warp = tid >> 5;
    const int u = lane >> 2, t = lane & 3;

    const float* gK = g_k + (size_t)bh * SEQ * DHEAD;
    const float* gV = g_v + (size_t)bh * DHEAD * SEQ;
    const float* gQ = g_q + (size_t)bh * SEQ * DHEAD;

    // Q fragments in registers (phi layout -> float2 gives logical (t, t+4))
    const int r = warp * 16 + u;
    float qa[8][4];
    {
        const float* qlo = gQ + (size_t)(q0 + r) * DHEAD;
        const float* qhi = qlo + 8 * DHEAD;
        #pragma unroll
        for (int kk = 0; kk < 8; kk++) {
            float2 lo = *(const float2*)(qlo + 8 * kk + 2 * t);
            float2 hi = *(const float2*)(qhi + 8 * kk + 2 * t);
            qa[kk][0] = lo.x; qa[kk][2] = lo.y;
            qa[kk][1] = hi.x; qa[kk][3] = hi.y;
        }
    }

    float o[8][4];
    #pragma unroll
    for (int j = 0; j < 8; j++)
        #pragma unroll
        for (int q = 0; q < 4; q++) o[j][q] = 0.f;
    float m0 = -1e30f, m1 = -1e30f, l0 = 0.f, l1 = 0.f;

    // tile loaders (swizzled cp.async)
    const int kRow = tid >> 1, kh = tid & 1;
    const int vRow = tid >> 2, vq = tid & 3;
    auto loadKV = [&](int kt, int buf) {
        const float* sK = gK + ((size_t)(kt * 128 + kRow)) * DHEAD + kh * 32;
        #pragma unroll
        for (int i = 0; i < 8; i++) {
            const int c = kh * 8 + i;
            cpa16(KsB + buf * 32768 + kRow * 256 + ((c ^ (kRow & 7)) << 4), sK + 4 * i);
        }
        const float* sV = gV + (size_t)vRow * SEQ + kt * 128 + vq * 32;
        #pragma unroll
        for (int i = 0; i < 8; i++) {
            const int c = vq * 8 + i;
            cpa16(VsB + buf * 32768 + vRow * 512 + ((c ^ (vRow & 7)) << 4), sV + 4 * i);
        }
        asm volatile("cp.async.commit_group;");
    };

    loadKV(0, 0);

    const int lrow = ((lane >> 3) & 1) * 8 + (lane & 7);
    const int lch  = lane >> 4;
    const uint32_t Pw = PsB + warp * 8192;   // this warp's P staging area

    for (int kt = 0; kt < SEQ / 128; ++kt) {
        const int cur = kt & 1;
        if (kt < SEQ / 128 - 1) loadKV(kt + 1, cur ^ 1);
        if (kt < SEQ / 128 - 1) asm volatile("cp.async.wait_group 1;");
        else                    asm volatile("cp.async.wait_group 0;");
        __syncthreads();

        // ---- S = Q K^T ----
        float sc[16][4];
        #pragma unroll
        for (int j = 0; j < 16; j++)
            #pragma unroll
            for (int q = 0; q < 4; q++) sc[j][q] = 0.f;

        const uint32_t Kb = KsB + cur * 32768;
        #pragma unroll
        for (int kk = 0; kk < 8; kk++) {
            #pragma unroll
            for (int jp = 0; jp < 8; jp++) {
                uint32_t b0, b1, b2, b3;
                const int rr = jp * 16 + lrow;
                const int c = 2 * kk + lch;
                ldsm4(b0, b1, b2, b3, Kb + rr * 256 + ((c ^ (rr & 7)) << 4));
                mma8f(sc[2 * jp],     qa[kk], b0, b2);
                mma8f(sc[2 * jp + 1], qa[kk], b1, b3);
            }
        }

        // ---- online softmax (base-2) ----
        float tm0 = -1e30f, tm1 = -1e30f;
        #pragma unroll
        for (int j = 0; j < 16; j++) {
            tm0 = fmaxf(tm0, fmaxf(sc[j][0], sc[j][1]));
            tm1 = fmaxf(tm1, fmaxf(sc[j][2], sc[j][3]));
        }
        tm0 = fmaxf(tm0, __shfl_xor_sync(0xffffffffu, tm0, 1));
        tm0 = fmaxf(tm0, __shfl_xor_sync(0xffffffffu, tm0, 2));
        tm1 = fmaxf(tm1, __shfl_xor_sync(0xffffffffu, tm1, 1));
        tm1 = fmaxf(tm1, __shfl_xor_sync(0xffffffffu, tm1, 2));

        const float nm0 = fmaxf(m0, tm0), nm1 = fmaxf(m1, tm1);
        const float al0 = ex2(m0 - nm0), al1 = ex2(m1 - nm1);
        m0 = nm0; m1 = nm1;

        float rs0 = 0.f, rs1 = 0.f;
        #pragma unroll
        for (int j = 0; j < 16; j++) {
            float p0 = tf32r(ex2(sc[j][0] - nm0));
            float p1 = tf32r(ex2(sc[j][1] - nm0));
            float p2 = tf32r(ex2(sc[j][2] - nm1));
            float p3 = tf32r(ex2(sc[j][3] - nm1));
            sc[j][0] = p0; sc[j][1] = p1; sc[j][2] = p2; sc[j][3] = p3;
            rs0 += p0 + p1; rs1 += p2 + p3;
        }
        rs0 += __shfl_xor_sync(0xffffffffu, rs0, 1);
        rs0 += __shfl_xor_sync(0xffffffffu, rs0, 2);
        rs1 += __shfl_xor_sync(0xffffffffu, rs1, 1);
        rs1 += __shfl_xor_sync(0xffffffffu, rs1, 2);
        l0 = l0 * al0 + rs0;
        l1 = l1 * al1 + rs1;

        #pragma unroll
        for (int j = 0; j < 8; j++) {
            o[j][0] *= al0; o[j][1] *= al0;
            o[j][2] *= al1; o[j][3] *= al1;
        }

        // ---- stage P to smem (c-frag layout -> natural [m][k]) ----
        #pragma unroll
        for (int j = 0; j < 16; j++) {
            const int ch = 2 * j + (t >> 1);
            const int wi = (t & 1) * 8;     // byte offset within chunk
            *(float2*)(sm + (Pw - sb) + u * 512 + ((ch ^ (u & 7)) << 4) + wi)
                = make_float2(sc[j][0], sc[j][1]);
            *(float2*)(sm + (Pw - sb) + (u + 8) * 512 + ((ch ^ ((u + 8) & 7)) << 4) + wi)
                = make_float2(sc[j][2], sc[j][3]);
        }
        __syncwarp();

        // ---- O += P V ----
        const uint32_t Vb = VsB + cur * 32768;
        #pragma unroll
        for (int kk = 0; kk < 16; kk++) {
            uint32_t a[4];
            {
                const int c = 2 * kk + lch;
                ldsm4(a[0], a[1], a[2], a[3],
                      Pw + lrow * 512 + ((c ^ (lrow & 7)) << 4));
            }
            #pragma unroll
            for (int jp = 0; jp < 4; jp++) {
                uint32_t b0, b1, b2, b3;
                const int rr = jp * 16 + lrow;
                const int c = 2 * kk + lch;
                ldsm4(b0, b1, b2, b3, Vb + rr * 512 + ((c ^ (rr & 7)) << 4));
                uint32_t bb0[2] = {b0, b2}, bb1[2] = {b1, b3};
                mma8(o[2 * jp],     a, bb0);
                mma8(o[2 * jp + 1], a, bb1);
            }
        }
        __syncthreads();
    }

    // ---- normalize, tf32-round, write ctx ----
    const float i0 = 1.0f / l0, i1 = 1.0f / l1;
    const int b_ = bh >> 4, h = bh & 15;
    const int row0 = q0 + r;
    #pragma unroll
    for (int j = 0; j < 8; j++) {
        const int d0 = 8 * j + 2 * t;
        float2 lo = make_float2(tf32r(o[j][0] * i0), tf32r(o[j][1] * i0));
        float2 hi = make_float2(tf32r(o[j][2] * i1), tf32r(o[j][3] * i1));
        *(float2*)&g_c[(size_t)(b_ * SEQ + row0) * DMODEL + h * DHEAD + d0] = lo;
        *(float2*)&g_c[(size_t)(b_ * SEQ + row0 + 8) * DMODEL + h * DHEAD + d0] = hi;
    }
}

// ============================================================================
extern "C" void kernel_launch(void* const* d_in, const int* in_sizes, int n_in,
                              void* d_out, int out_size)
{
    const float* x  = (const float*)d_in[0];
    const float* Wq = (const float*)d_in[1];
    const float* Wk = (const float*)d_in[2];
    const float* Wv = (const float*)d_in[3];
    const float* Wo = (const float*)d_in[4];
    float* out = (float*)d_out;

    static int attr_set = 0;
    if (!attr_set) {
        cudaFuncSetAttribute(k_flash, cudaFuncAttributeMaxDynamicSharedMemorySize, SMEM_FLASH);
        cudaFuncSetAttribute(k_proj, cudaFuncAttributeMaxDynamicSharedMemorySize, 65536);
        attr_set = 1;
    }

    k_roundx<<<8192, 256>>>((const float4*)x);
    k_trw<<<dim3(32, 32, 4), dim3(32, 8)>>>(Wq, Wk, Wv, Wo);
    k_proj<<<dim3(8, 64, 3), 256, 65536>>>(0, nullptr);
    k_flash<<<dim3(16, 64), 256, SMEM_FLASH>>>();
    k_proj<<<dim3(8, 64, 1), 256, 65536>>>(3, out);
}